// round 1
// baseline (speedup 1.0000x reference)
#include <cuda_runtime.h>

#define THREADS 512
#define PTS 128
#define ENC_STRIDE 97   // 96 + 1 pad: (l*97 + k) % 32 distinct per lane
#define H_STRIDE 129    // 128 + 1 pad

// shared memory float-offsets
#define OFF_ENC 0
#define SZ_ENC (PTS * ENC_STRIDE)          // 12416
#define OFF_H   (OFF_ENC + SZ_ENC)
#define SZ_H   (PTS * H_STRIDE)            // 16512
#define OFF_WC  (OFF_H + SZ_H)             // weight chunk double buffer
#define SZ_WC  (2 * 32 * 128)              // 8192
#define OFF_WL  (OFF_WC + SZ_WC)
#define SZ_WL  (224 * 4)
#define OFF_BL  (OFF_WL + SZ_WL)
#define SMEM_FLOATS (OFF_BL + 4)           // 38020 floats = 152080 B

typedef unsigned long long ull;

__device__ __forceinline__ ull pack2(float a, float b) {
    ull r; asm("mov.b64 %0, {%1, %2};" : "=l"(r) : "f"(a), "f"(b)); return r;
}
__device__ __forceinline__ void unpack2(ull v, float& a, float& b) {
    asm("mov.b64 {%0, %1}, %2;" : "=f"(a), "=f"(b) : "l"(v));
}
// Blackwell packed fp32x2 FMA: 2 IEEE fp32 FMAs per lane per instruction.
__device__ __forceinline__ void fma2(ull& d, ull a, ull b) {
    asm("fma.rn.f32x2 %0, %1, %2, %0;" : "+l"(d) : "l"(a), "l"(b));
}
__device__ __forceinline__ unsigned s2u(const void* p) {
    return (unsigned)__cvta_generic_to_shared(p);
}
__device__ __forceinline__ void cp16(unsigned s, const void* g) {
    asm volatile("cp.async.cg.shared.global [%0], [%1], 16;" :: "r"(s), "l"(g));
}
__device__ __forceinline__ void cp_commit() { asm volatile("cp.async.commit_group;"); }
__device__ __forceinline__ void cp_wait0()  { asm volatile("cp.async.wait_group 0;"); }
__device__ __forceinline__ void cp_wait1()  { asm volatile("cp.async.wait_group 1;"); }

__global__ void __launch_bounds__(THREADS, 1)
nf_kernel(const float* __restrict__ qp,
          const float* __restrict__ W0, const float* __restrict__ b0,
          const float* __restrict__ Wh, const float* __restrict__ bh,
          const float* __restrict__ Wl, const float* __restrict__ bl,
          float* __restrict__ out)
{
    extern __shared__ float sm[];
    float* ENCs = sm + OFF_ENC;   // [128][97]  frequency encoding (static per CTA)
    float* Hs   = sm + OFF_H;     // [128][129] hidden activations
    float* WC   = sm + OFF_WC;    // [2][32][128] weight chunk double buffer
    float* WLs  = sm + OFF_WL;    // [224][4]
    float* BLs  = sm + OFF_BL;    // [4]

    const int tid  = threadIdx.x;
    const int lane = tid & 31;
    const int nb   = (tid >> 5) * 8;        // 16 warps x 8 neurons = 128
    const int gp0  = blockIdx.x * PTS;

    // stage final-layer weights
    for (int i = tid; i < SZ_WL; i += THREADS) WLs[i] = Wl[i];
    if (tid < 4) BLs[tid] = bl[tid];

    // NeRF frequency encoding: matches jax bit-for-bit up to sincosf's ~2ulp.
    // freqs_l = fl(2^l * pi_f32) is exact (power-of-2 scale); xf = fl(x*freq).
    for (int idx = tid; idx < PTS * 48; idx += THREADS) {
        int p = idx / 48;
        int r = idx - p * 48;
        int c = r >> 4, l = r & 15;
        float x = __ldg(qp + (gp0 + p) * 3 + c);
        float f = (float)(1 << l) * 3.14159265358979323846f;
        float s, co;
        sincosf(x * f, &s, &co);
        ENCs[p * ENC_STRIDE + c * 32 + l]      = s;
        ENCs[p * ENC_STRIDE + c * 32 + 16 + l] = co;
    }
    __syncthreads();

    ull acc[4][4];  // [point i][neuron-pair j] fp32x2 accumulators

    auto load_chunk = [&](const float* Wg, int c, int buf) {
        unsigned d = s2u(WC + buf * 4096) + tid * 16;
        const char* g = (const char*)(Wg + c * 4096) + tid * 16;
        cp16(d, g);
        cp16(d + 8192, g + 8192);
        cp_commit();
    };

    // per lane per k: 4 LDS.32 (x) + 4 packs + 4 broadcast LDS.64 (w) + 16 FFMA2 = 32 MAC
    auto compute_chunk = [&](const float* xreg, int xstr, int koff, int buf) {
        const float* xs0 = xreg + lane * xstr + koff;
        const float* xs1 = xs0 + 32 * xstr;
        const float* xs2 = xs1 + 32 * xstr;
        const float* xs3 = xs2 + 32 * xstr;
        const float* wrow = WC + buf * 4096 + nb;
        #pragma unroll 8
        for (int kc = 0; kc < 32; kc++) {
            float x0 = xs0[kc], x1 = xs1[kc], x2 = xs2[kc], x3 = xs3[kc];
            ull X0 = pack2(x0, x0), X1 = pack2(x1, x1);
            ull X2 = pack2(x2, x2), X3 = pack2(x3, x3);
            const ull* wp = (const ull*)(wrow + kc * 128);
            ull w0 = wp[0], w1 = wp[1], w2 = wp[2], w3 = wp[3];
            fma2(acc[0][0], X0, w0); fma2(acc[0][1], X0, w1); fma2(acc[0][2], X0, w2); fma2(acc[0][3], X0, w3);
            fma2(acc[1][0], X1, w0); fma2(acc[1][1], X1, w1); fma2(acc[1][2], X1, w2); fma2(acc[1][3], X1, w3);
            fma2(acc[2][0], X2, w0); fma2(acc[2][1], X2, w1); fma2(acc[2][2], X2, w2); fma2(acc[2][3], X2, w3);
            fma2(acc[3][0], X3, w0); fma2(acc[3][1], X3, w1); fma2(acc[3][2], X3, w2); fma2(acc[3][3], X3, w3);
        }
    };

    auto run_layer = [&](const float* Wg, const float* bias, int nch, bool is_l0) {
        #pragma unroll
        for (int i = 0; i < 4; i++)
            #pragma unroll
            for (int j = 0; j < 4; j++) acc[i][j] = 0ULL;

        load_chunk(Wg, 0, 0);
        for (int c = 0; c < nch; c++) {
            if (c + 1 < nch) { load_chunk(Wg, c + 1, (c + 1) & 1); cp_wait1(); }
            else             { cp_wait0(); }
            __syncthreads();
            int koff = c * 32;
            if (is_l0)           compute_chunk(ENCs, ENC_STRIDE, koff, c & 1);
            else if (koff < 128) compute_chunk(Hs,   H_STRIDE,   koff, c & 1);
            else                 compute_chunk(ENCs, ENC_STRIDE, koff - 128, c & 1);
            __syncthreads();   // all reads of this buf done before it is refilled
        }

        // bias + ReLU + writeback (all reads of Hs finished at last barrier)
        float bb[8];
        #pragma unroll
        for (int n = 0; n < 8; n++) bb[n] = __ldg(bias + nb + n);
        #pragma unroll
        for (int i = 0; i < 4; i++) {
            float* hp = Hs + (lane + 32 * i) * H_STRIDE + nb;
            #pragma unroll
            for (int j = 0; j < 4; j++) {
                float v0, v1; unpack2(acc[i][j], v0, v1);
                hp[2 * j]     = fmaxf(v0 + bb[2 * j],     0.f);
                hp[2 * j + 1] = fmaxf(v1 + bb[2 * j + 1], 0.f);
            }
        }
        __syncthreads();
    };

    // layer 0: enc[96] -> 128, then 7 hidden layers: [H|enc][224] -> 128
    run_layer(W0, b0, 3, true);
    for (int L = 0; L < 7; L++)
        run_layer(Wh + L * 224 * 128, bh + L * 128, 7, false);

    // output layer: [H|enc][224] -> 4, no activation
    {
        int p = tid >> 2, j = tid & 3;
        float a = BLs[j];
        const float* hp = Hs   + p * H_STRIDE;
        const float* ep = ENCs + p * ENC_STRIDE;
        #pragma unroll 8
        for (int k = 0; k < 128; k++) a = fmaf(hp[k], WLs[k * 4 + j], a);
        #pragma unroll 8
        for (int k = 0; k < 96;  k++) a = fmaf(ep[k], WLs[(128 + k) * 4 + j], a);
        out[(gp0 + p) * 4 + j] = a;
    }
}

extern "C" void kernel_launch(void* const* d_in, const int* in_sizes, int n_in,
                              void* d_out, int out_size) {
    const float* qp = (const float*)d_in[0];
    const float* W0 = (const float*)d_in[1];
    const float* b0 = (const float*)d_in[2];
    const float* Wh = (const float*)d_in[3];
    const float* bh = (const float*)d_in[4];
    const float* Wl = (const float*)d_in[5];
    const float* bl = (const float*)d_in[6];
    float* out = (float*)d_out;

    int n = in_sizes[0] / 3;                 // 524288
    size_t smem = SMEM_FLOATS * sizeof(float);
    cudaFuncSetAttribute(nf_kernel, cudaFuncAttributeMaxDynamicSharedMemorySize, (int)smem);
    nf_kernel<<<n / PTS, THREADS, smem>>>(qp, W0, b0, Wh, bh, Wl, bl, out);
}

// round 2
// speedup vs baseline: 1.0010x; 1.0010x over previous
#include <cuda_runtime.h>

#define THREADS 512
#define PTS 128
#define ENC_STRIDE 97   // 96 + 1 pad: (l*97 + k) % 32 distinct per lane
#define H_STRIDE 129    // 128 + 1 pad

// shared memory float-offsets
#define OFF_ENC 0
#define SZ_ENC (PTS * ENC_STRIDE)          // 12416
#define OFF_H   (OFF_ENC + SZ_ENC)
#define SZ_H   (PTS * H_STRIDE)            // 16512
#define OFF_WC  (OFF_H + SZ_H)             // weight chunk double buffer
#define SZ_WC  (2 * 32 * 128)              // 8192
#define OFF_WL  (OFF_WC + SZ_WC)
#define SZ_WL  (224 * 4)
#define OFF_BL  (OFF_WL + SZ_WL)
#define SMEM_FLOATS (OFF_BL + 4)           // 38020 floats = 152080 B

typedef unsigned long long ull;

__device__ __forceinline__ ull pack2(float a, float b) {
    ull r; asm("mov.b64 %0, {%1, %2};" : "=l"(r) : "f"(a), "f"(b)); return r;
}
__device__ __forceinline__ void unpack2(ull v, float& a, float& b) {
    asm("mov.b64 {%0, %1}, %2;" : "=f"(a), "=f"(b) : "l"(v));
}
// Blackwell packed fp32x2 FMA: 2 IEEE fp32 FMAs per lane per instruction.
__device__ __forceinline__ void fma2(ull& d, ull a, ull b) {
    asm("fma.rn.f32x2 %0, %1, %2, %0;" : "+l"(d) : "l"(a), "l"(b));
}
__device__ __forceinline__ unsigned s2u(const void* p) {
    return (unsigned)__cvta_generic_to_shared(p);
}
__device__ __forceinline__ void cp16(unsigned s, const void* g) {
    asm volatile("cp.async.cg.shared.global [%0], [%1], 16;" :: "r"(s), "l"(g));
}
__device__ __forceinline__ void cp_commit() { asm volatile("cp.async.commit_group;"); }
__device__ __forceinline__ void cp_wait0()  { asm volatile("cp.async.wait_group 0;"); }
__device__ __forceinline__ void cp_wait1()  { asm volatile("cp.async.wait_group 1;"); }

__global__ void __launch_bounds__(THREADS, 1)
nf_kernel(const float* __restrict__ qp,
          const float* __restrict__ W0, const float* __restrict__ b0,
          const float* __restrict__ Wh, const float* __restrict__ bh,
          const float* __restrict__ Wl, const float* __restrict__ bl,
          float* __restrict__ out)
{
    extern __shared__ float sm[];
    float* ENCs = sm + OFF_ENC;   // [128][97]  frequency encoding (static per CTA)
    float* Hs   = sm + OFF_H;     // [128][129] hidden activations
    float* WC   = sm + OFF_WC;    // [2][32][128] weight chunk double buffer
    float* WLs  = sm + OFF_WL;    // [224][4]
    float* BLs  = sm + OFF_BL;    // [4]

    const int tid  = threadIdx.x;
    const int lane = tid & 31;
    const int nb   = (tid >> 5) * 8;        // 16 warps x 8 neurons = 128
    const int gp0  = blockIdx.x * PTS;

    // stage final-layer weights
    for (int i = tid; i < SZ_WL; i += THREADS) WLs[i] = Wl[i];
    if (tid < 4) BLs[tid] = bl[tid];

    // NeRF frequency encoding: matches jax bit-for-bit up to sincosf's ~2ulp.
    // freqs_l = fl(2^l * pi_f32) is exact (power-of-2 scale); xf = fl(x*freq).
    for (int idx = tid; idx < PTS * 48; idx += THREADS) {
        int p = idx / 48;
        int r = idx - p * 48;
        int c = r >> 4, l = r & 15;
        float x = __ldg(qp + (gp0 + p) * 3 + c);
        float f = (float)(1 << l) * 3.14159265358979323846f;
        float s, co;
        sincosf(x * f, &s, &co);
        ENCs[p * ENC_STRIDE + c * 32 + l]      = s;
        ENCs[p * ENC_STRIDE + c * 32 + 16 + l] = co;
    }
    __syncthreads();

    ull acc[4][4];  // [point i][neuron-pair j] fp32x2 accumulators

    auto load_chunk = [&](const float* Wg, int c, int buf) {
        unsigned d = s2u(WC + buf * 4096) + tid * 16;
        const char* g = (const char*)(Wg + c * 4096) + tid * 16;
        cp16(d, g);
        cp16(d + 8192, g + 8192);
        cp_commit();
    };

    // per lane per k: 4 LDS.32 (x) + 4 packs + 4 broadcast LDS.64 (w) + 16 FFMA2 = 32 MAC
    auto compute_chunk = [&](const float* xreg, int xstr, int koff, int buf) {
        const float* xs0 = xreg + lane * xstr + koff;
        const float* xs1 = xs0 + 32 * xstr;
        const float* xs2 = xs1 + 32 * xstr;
        const float* xs3 = xs2 + 32 * xstr;
        const float* wrow = WC + buf * 4096 + nb;
        #pragma unroll 8
        for (int kc = 0; kc < 32; kc++) {
            float x0 = xs0[kc], x1 = xs1[kc], x2 = xs2[kc], x3 = xs3[kc];
            ull X0 = pack2(x0, x0), X1 = pack2(x1, x1);
            ull X2 = pack2(x2, x2), X3 = pack2(x3, x3);
            const ull* wp = (const ull*)(wrow + kc * 128);
            ull w0 = wp[0], w1 = wp[1], w2 = wp[2], w3 = wp[3];
            fma2(acc[0][0], X0, w0); fma2(acc[0][1], X0, w1); fma2(acc[0][2], X0, w2); fma2(acc[0][3], X0, w3);
            fma2(acc[1][0], X1, w0); fma2(acc[1][1], X1, w1); fma2(acc[1][2], X1, w2); fma2(acc[1][3], X1, w3);
            fma2(acc[2][0], X2, w0); fma2(acc[2][1], X2, w1); fma2(acc[2][2], X2, w2); fma2(acc[2][3], X2, w3);
            fma2(acc[3][0], X3, w0); fma2(acc[3][1], X3, w1); fma2(acc[3][2], X3, w2); fma2(acc[3][3], X3, w3);
        }
    };

    auto run_layer = [&](const float* Wg, const float* bias, int nch, bool is_l0) {
        #pragma unroll
        for (int i = 0; i < 4; i++)
            #pragma unroll
            for (int j = 0; j < 4; j++) acc[i][j] = 0ULL;

        load_chunk(Wg, 0, 0);
        for (int c = 0; c < nch; c++) {
            if (c + 1 < nch) { load_chunk(Wg, c + 1, (c + 1) & 1); cp_wait1(); }
            else             { cp_wait0(); }
            __syncthreads();
            int koff = c * 32;
            if (is_l0)           compute_chunk(ENCs, ENC_STRIDE, koff, c & 1);
            else if (koff < 128) compute_chunk(Hs,   H_STRIDE,   koff, c & 1);
            else                 compute_chunk(ENCs, ENC_STRIDE, koff - 128, c & 1);
            __syncthreads();   // all reads of this buf done before it is refilled
        }

        // bias + ReLU + writeback (all reads of Hs finished at last barrier)
        float bb[8];
        #pragma unroll
        for (int n = 0; n < 8; n++) bb[n] = __ldg(bias + nb + n);
        #pragma unroll
        for (int i = 0; i < 4; i++) {
            float* hp = Hs + (lane + 32 * i) * H_STRIDE + nb;
            #pragma unroll
            for (int j = 0; j < 4; j++) {
                float v0, v1; unpack2(acc[i][j], v0, v1);
                hp[2 * j]     = fmaxf(v0 + bb[2 * j],     0.f);
                hp[2 * j + 1] = fmaxf(v1 + bb[2 * j + 1], 0.f);
            }
        }
        __syncthreads();
    };

    // layer 0: enc[96] -> 128, then 7 hidden layers: [H|enc][224] -> 128
    run_layer(W0, b0, 3, true);
    for (int L = 0; L < 7; L++)
        run_layer(Wh + L * 224 * 128, bh + L * 128, 7, false);

    // output layer: [H|enc][224] -> 4, no activation
    {
        int p = tid >> 2, j = tid & 3;
        float a = BLs[j];
        const float* hp = Hs   + p * H_STRIDE;
        const float* ep = ENCs + p * ENC_STRIDE;
        #pragma unroll 8
        for (int k = 0; k < 128; k++) a = fmaf(hp[k], WLs[k * 4 + j], a);
        #pragma unroll 8
        for (int k = 0; k < 96;  k++) a = fmaf(ep[k], WLs[(128 + k) * 4 + j], a);
        out[(gp0 + p) * 4 + j] = a;
    }
}

extern "C" void kernel_launch(void* const* d_in, const int* in_sizes, int n_in,
                              void* d_out, int out_size) {
    const float* qp = (const float*)d_in[0];
    const float* W0 = (const float*)d_in[1];
    const float* b0 = (const float*)d_in[2];
    const float* Wh = (const float*)d_in[3];
    const float* bh = (const float*)d_in[4];
    const float* Wl = (const float*)d_in[5];
    const float* bl = (const float*)d_in[6];
    float* out = (float*)d_out;

    int n = in_sizes[0] / 3;                 // 524288
    size_t smem = SMEM_FLOATS * sizeof(float);
    cudaFuncSetAttribute(nf_kernel, cudaFuncAttributeMaxDynamicSharedMemorySize, (int)smem);
    nf_kernel<<<n / PTS, THREADS, smem>>>(qp, W0, b0, Wh, bh, Wl, bl, out);
}

// round 4
// speedup vs baseline: 2.6832x; 2.6806x over previous
#include <cuda_runtime.h>
#include <cuda_bf16.h>
#include <cstdint>

#define THREADS 256
#define NPTS 128
#define PI_F 3.14159265358979323846f

// ---------------- pre-formatted weight scratch (B-fragment order) -------------
// hidden layer l (0..6): base l*114688, chunk c (32 neurons): +c*28672
//   frag (j,nb,plane): offset ((j*4+nb)*2+plane)*256 + lane*8 + reg*4 + (k&1)*2
// layer0: base G_L0, chunk stride 12288 (j 0..5)
// final : base G_FIN, frag (j*2+plane)*256 (single n-block, n>=4 zero)
#define L_STRIDE   114688u
#define C_STRIDE   28672u
#define G_L0       802816u
#define L0_CSTRIDE 12288u
#define G_FIN      851968u
#define G_TOT      859136u
__device__ __align__(16) unsigned char g_wt[G_TOT];

// ---------------- smem (bytes) -------------------------------------------------
#define OFF_RING 0u          // 2 x 28672 weight chunk ring
#define OFF_ENC  57344u      // enc A-frags: 8 warps x 6 j x 2 planes x 512B
#define OFF_BIAS 106496u     // 1028 floats
#define SMEM_TOT 110608u

// ---------------- helpers ------------------------------------------------------
__device__ __forceinline__ void mma_bf16(float* d, const uint32_t* a, uint32_t b0, uint32_t b1){
    asm("mma.sync.aligned.m16n8k16.row.col.f32.bf16.bf16.f32 "
        "{%0,%1,%2,%3},{%4,%5,%6,%7},{%8,%9},{%0,%1,%2,%3};"
        : "+f"(d[0]), "+f"(d[1]), "+f"(d[2]), "+f"(d[3])
        : "r"(a[0]), "r"(a[1]), "r"(a[2]), "r"(a[3]), "r"(b0), "r"(b1));
}
__device__ __forceinline__ void cp16(uint32_t s, const void* g){
    asm volatile("cp.async.cg.shared.global [%0], [%1], 16;" :: "r"(s), "l"(g));
}
__device__ __forceinline__ void split2(float v0, float v1, uint32_t& h, uint32_t& l){
    __nv_bfloat16 h0 = __float2bfloat16(v0), h1 = __float2bfloat16(v1);
    __nv_bfloat162 hp = __halves2bfloat162(h0, h1);
    __nv_bfloat162 lp = __halves2bfloat162(__float2bfloat16(v0 - __bfloat162float(h0)),
                                           __float2bfloat16(v1 - __bfloat162float(h1)));
    h = *(uint32_t*)&hp; l = *(uint32_t*)&lp;
}

// ---------------- prep: fp32 weights -> split-bf16 B-fragment order -----------
__global__ void prep_kernel(const float* __restrict__ W0, const float* __restrict__ Wh,
                            const float* __restrict__ Wl){
    int i = blockIdx.x * blockDim.x + threadIdx.x;
    const int NH = 7 * 28672, NL0 = 96 * 128, NF = 224 * 8;
    if (i >= NH + NL0 + NF) return;
    float v; uint32_t addr; int k, n;
    if (i < NH){
        int l = i / 28672, r = i % 28672; k = r / 128; n = r % 128;
        v = Wh[(l * 224 + k) * 128 + n];
        addr = (uint32_t)l * L_STRIDE + (uint32_t)(n >> 5) * C_STRIDE
             + (uint32_t)(((k >> 4) * 4 + ((n >> 3) & 3)) * 2) * 256u;
    } else if (i < NH + NL0){
        int q = i - NH; k = q / 128; n = q % 128;
        v = W0[k * 128 + n];
        addr = G_L0 + (uint32_t)(n >> 5) * L0_CSTRIDE
             + (uint32_t)(((k >> 4) * 4 + ((n >> 3) & 3)) * 2) * 256u;
    } else {
        int q = i - NH - NL0; k = q / 8; n = q % 8;
        v = (n < 4) ? Wl[k * 4 + n] : 0.0f;
        addr = G_FIN + (uint32_t)((k >> 4) * 2) * 256u;
    }
    uint32_t sub = (uint32_t)((n & 7) * 4 + ((k & 7) >> 1)) * 8u
                 + (uint32_t)((k >> 3) & 1) * 4u + (uint32_t)(k & 1) * 2u;
    __nv_bfloat16 hi = __float2bfloat16(v);
    __nv_bfloat16 lo = __float2bfloat16(v - __bfloat162float(hi));
    *(__nv_bfloat16*)(g_wt + addr + sub)        = hi;
    *(__nv_bfloat16*)(g_wt + addr + 256u + sub) = lo;
}

// ---------------- main fused kernel --------------------------------------------
__global__ void __launch_bounds__(THREADS, 1)
nf_main(const float* __restrict__ qp, const float* __restrict__ b0g,
        const float* __restrict__ bhg, const float* __restrict__ blg,
        float* __restrict__ out)
{
    extern __shared__ char smc[];
    const int tid = threadIdx.x, w = tid >> 5, lane = tid & 31;
    const int l4 = lane >> 2, lm = lane & 3;
    const int gp0 = blockIdx.x * NPTS;
    const uint32_t sb = (uint32_t)__cvta_generic_to_shared(smc);

    float* bias = (float*)(smc + OFF_BIAS);
    for (int i = tid; i < 1028; i += THREADS)
        bias[i] = (i < 128) ? b0g[i] : (i < 1024 ? bhg[i - 128] : blg[i - 1024]);

    // ---- NeRF encoding directly into A-fragment order (hi/lo planes) ----
    {
        float xa[2][3];
        #pragma unroll
        for (int r = 0; r < 2; r++)
            #pragma unroll
            for (int c = 0; c < 3; c++)
                xa[r][c] = __ldg(qp + (gp0 + w * 16 + l4 + r * 8) * 3 + c);
        #pragma unroll
        for (int j = 0; j < 6; j++){
            uint32_t H[4], L[4];
            #pragma unroll
            for (int g = 0; g < 2; g++){
                int kb = 16 * j + 2 * lm + g * 8;
                #pragma unroll
                for (int r = 0; r < 2; r++){
                    float v[2];
                    #pragma unroll
                    for (int e = 0; e < 2; e++){
                        int k = kb + e, c = k >> 5, t = k & 31;
                        float s, co;
                        sincosf(xa[r][c] * ((float)(1 << (t & 15)) * PI_F), &s, &co);
                        v[e] = (t < 16) ? s : co;
                    }
                    split2(v[0], v[1], H[g * 2 + r], L[g * 2 + r]);
                }
            }
            char* eb = smc + OFF_ENC + (uint32_t)((w * 6 + j) * 2) * 512u + lane * 16;
            *(uint4*)eb         = *(uint4*)H;
            *(uint4*)(eb + 512) = *(uint4*)L;
        }
    }
    __syncthreads();

    float acc[16][4];
    uint32_t Ah[8][4], Al[8][4];

    auto zero_acc = [&](){
        #pragma unroll
        for (int i = 0; i < 16; i++){ acc[i][0] = 0; acc[i][1] = 0; acc[i][2] = 0; acc[i][3] = 0; }
    };
    auto load_chunk = [&](const unsigned char* src, uint32_t bytes, int buf){
        uint32_t dst = sb + OFF_RING + (uint32_t)buf * C_STRIDE;
        for (uint32_t i = (uint32_t)tid * 16u; i < bytes; i += THREADS * 16u)
            cp16(dst + i, src + i);
        asm volatile("cp.async.commit_group;");
    };
    auto ldenc = [&](int j, uint32_t* H, uint32_t* L){
        const char* eb = smc + OFF_ENC + (uint32_t)((w * 6 + j) * 2) * 512u + lane * 16;
        *(uint4*)H = *(const uint4*)eb;
        *(uint4*)L = *(const uint4*)(eb + 512);
    };
    // one (j, chunk) step: 4 n-blocks x 3 passes = 12 MMAs, 8 LDS.64
    auto nb_block = [&](const char* fb, const uint32_t* AH, const uint32_t* AL, int cb){
        uint64_t b0 = *(const uint64_t*)(fb);
        uint64_t b1 = *(const uint64_t*)(fb + 512);
        uint64_t b2 = *(const uint64_t*)(fb + 1024);
        uint64_t b3 = *(const uint64_t*)(fb + 1536);
        mma_bf16(acc[cb+0], AH, (uint32_t)b0, (uint32_t)(b0 >> 32));
        mma_bf16(acc[cb+1], AH, (uint32_t)b1, (uint32_t)(b1 >> 32));
        mma_bf16(acc[cb+2], AH, (uint32_t)b2, (uint32_t)(b2 >> 32));
        mma_bf16(acc[cb+3], AH, (uint32_t)b3, (uint32_t)(b3 >> 32));
        mma_bf16(acc[cb+0], AL, (uint32_t)b0, (uint32_t)(b0 >> 32));
        mma_bf16(acc[cb+1], AL, (uint32_t)b1, (uint32_t)(b1 >> 32));
        mma_bf16(acc[cb+2], AL, (uint32_t)b2, (uint32_t)(b2 >> 32));
        mma_bf16(acc[cb+3], AL, (uint32_t)b3, (uint32_t)(b3 >> 32));
        uint64_t c0 = *(const uint64_t*)(fb + 256);
        uint64_t c1 = *(const uint64_t*)(fb + 768);
        uint64_t c2 = *(const uint64_t*)(fb + 1280);
        uint64_t c3 = *(const uint64_t*)(fb + 1792);
        mma_bf16(acc[cb+0], AH, (uint32_t)c0, (uint32_t)(c0 >> 32));
        mma_bf16(acc[cb+1], AH, (uint32_t)c1, (uint32_t)(c1 >> 32));
        mma_bf16(acc[cb+2], AH, (uint32_t)c2, (uint32_t)(c2 >> 32));
        mma_bf16(acc[cb+3], AH, (uint32_t)c3, (uint32_t)(c3 >> 32));
    };
    auto epilogue = [&](const float* bp){
        #pragma unroll
        for (int j = 0; j < 8; j++){
            float ba0 = bp[16*j + 2*lm],     ba1 = bp[16*j + 2*lm + 1];
            float bb0 = bp[16*j + 8 + 2*lm], bb1 = bp[16*j + 8 + 2*lm + 1];
            float v0 = fmaxf(acc[2*j][0] + ba0, 0.f);
            float v1 = fmaxf(acc[2*j][1] + ba1, 0.f);
            float v2 = fmaxf(acc[2*j][2] + ba0, 0.f);
            float v3 = fmaxf(acc[2*j][3] + ba1, 0.f);
            float u0 = fmaxf(acc[2*j+1][0] + bb0, 0.f);
            float u1 = fmaxf(acc[2*j+1][1] + bb1, 0.f);
            float u2 = fmaxf(acc[2*j+1][2] + bb0, 0.f);
            float u3 = fmaxf(acc[2*j+1][3] + bb1, 0.f);
            split2(v0, v1, Ah[j][0], Al[j][0]);
            split2(v2, v3, Ah[j][1], Al[j][1]);
            split2(u0, u1, Ah[j][2], Al[j][2]);
            split2(u2, u3, Ah[j][3], Al[j][3]);
        }
    };

    // ---- layer 0: enc(96) -> 128 ----
    zero_acc();
    load_chunk(g_wt + G_L0, L0_CSTRIDE, 0);
    #pragma unroll
    for (int c = 0; c < 4; c++){
        if (c < 3){ load_chunk(g_wt + G_L0 + (uint32_t)(c + 1) * L0_CSTRIDE, L0_CSTRIDE, (c + 1) & 1);
                    asm volatile("cp.async.wait_group 1;"); }
        else        asm volatile("cp.async.wait_group 0;");
        __syncthreads();
        {
            const char* rb = smc + OFF_RING + (uint32_t)(c & 1) * C_STRIDE;
            #pragma unroll
            for (int j = 0; j < 6; j++){
                uint32_t EH[4], EL[4]; ldenc(j, EH, EL);
                nb_block(rb + (uint32_t)(j * 4) * 512u + lane * 8, EH, EL, 4 * c);
            }
        }
        __syncthreads();
    }
    epilogue(bias);

    // ---- 7 hidden layers: [H(128)|enc(96)] -> 128 ----
    for (int l = 0; l < 7; l++){
        zero_acc();
        const unsigned char* ws = g_wt + (uint32_t)l * L_STRIDE;
        load_chunk(ws, C_STRIDE, 0);
        #pragma unroll
        for (int c = 0; c < 4; c++){
            if (c < 3){ load_chunk(ws + (uint32_t)(c + 1) * C_STRIDE, C_STRIDE, (c + 1) & 1);
                        asm volatile("cp.async.wait_group 1;"); }
            else        asm volatile("cp.async.wait_group 0;");
            __syncthreads();
            {
                const char* rb = smc + OFF_RING + (uint32_t)(c & 1) * C_STRIDE;
                #pragma unroll
                for (int j = 0; j < 14; j++){
                    const uint32_t *pAH, *pAL; uint32_t EH[4], EL[4];
                    if (j < 8){ pAH = Ah[j]; pAL = Al[j]; }
                    else      { ldenc(j - 8, EH, EL); pAH = EH; pAL = EL; }
                    nb_block(rb + (uint32_t)(j * 4) * 512u + lane * 8, pAH, pAL, 4 * c);
                }
            }
            __syncthreads();
        }
        epilogue(bias + 128 + l * 128);
    }

    // ---- final layer: [H|enc](224) -> 4 (N padded to 8) ----
    load_chunk(g_wt + G_FIN, 7168u, 0);
    asm volatile("cp.async.wait_group 0;");
    __syncthreads();
    float fac[4] = {0.f, 0.f, 0.f, 0.f};
    {
        const char* rb = smc + OFF_RING;
        #pragma unroll
        for (int j = 0; j < 14; j++){
            const uint32_t *pAH, *pAL; uint32_t EH[4], EL[4];
            if (j < 8){ pAH = Ah[j]; pAL = Al[j]; }
            else      { ldenc(j - 8, EH, EL); pAH = EH; pAL = EL; }
            const char* fb = rb + (uint32_t)(j * 2) * 256u + lane * 8;
            uint64_t bh = *(const uint64_t*)fb;
            uint64_t bl2 = *(const uint64_t*)(fb + 256);
            mma_bf16(fac, pAH, (uint32_t)bh,  (uint32_t)(bh  >> 32));
            mma_bf16(fac, pAL, (uint32_t)bh,  (uint32_t)(bh  >> 32));
            mma_bf16(fac, pAH, (uint32_t)bl2, (uint32_t)(bl2 >> 32));
        }
    }
    if (lm < 2){
        int n0 = 2 * lm;
        float bv0 = bias[1024 + n0], bv1 = bias[1024 + n0 + 1];
        int p0 = gp0 + w * 16 + l4;
        *(float2*)(out + p0 * 4 + n0)       = make_float2(fac[0] + bv0, fac[1] + bv1);
        *(float2*)(out + (p0 + 8) * 4 + n0) = make_float2(fac[2] + bv0, fac[3] + bv1);
    }
}

extern "C" void kernel_launch(void* const* d_in, const int* in_sizes, int n_in,
                              void* d_out, int out_size) {
    const float* qp = (const float*)d_in[0];
    const float* W0 = (const float*)d_in[1];
    const float* b0 = (const float*)d_in[2];
    const float* Wh = (const float*)d_in[3];
    const float* bh = (const float*)d_in[4];
    const float* Wl = (const float*)d_in[5];
    const float* bl = (const float*)d_in[6];
    float* out = (float*)d_out;

    int n = in_sizes[0] / 3;   // 524288
    const int NPREP = 7 * 28672 + 96 * 128 + 224 * 8;
    prep_kernel<<<(NPREP + 255) / 256, 256>>>(W0, Wh, Wl);
    cudaFuncSetAttribute(nf_main, cudaFuncAttributeMaxDynamicSharedMemorySize, (int)SMEM_TOT);
    nf_main<<<n / NPTS, THREADS, SMEM_TOT>>>(qp, b0, bh, bl, out);
}

// round 5
// speedup vs baseline: 2.6838x; 1.0002x over previous
#include <cuda_runtime.h>
#include <cuda_bf16.h>
#include <cstdint>

#define THREADS 256
#define NPTS 128
#define PI_F 3.14159265358979323846f

// ---------------- pre-formatted weight scratch (B-fragment order) -------------
// hidden layer l (0..6): base l*114688, chunk c (32 neurons): +c*28672
//   frag (j,nb,plane): offset ((j*4+nb)*2+plane)*256 + lane*8 + reg*4 + (k&1)*2
// layer0: base G_L0, chunk stride 12288 (j 0..5)
// final : base G_FIN, frag (j*2+plane)*256 (single n-block, n>=4 zero)
#define L_STRIDE   114688u
#define C_STRIDE   28672u
#define G_L0       802816u
#define L0_CSTRIDE 12288u
#define G_FIN      851968u
#define G_TOT      859136u
__device__ __align__(16) unsigned char g_wt[G_TOT];

// ---------------- smem (bytes) -------------------------------------------------
#define OFF_RING 0u          // 2 x 28672 weight chunk ring
#define OFF_ENC  57344u      // enc A-frags: 8 warps x 6 j x 2 planes x 512B
#define OFF_BIAS 106496u     // 1028 floats
#define SMEM_TOT 110608u

// ---------------- helpers ------------------------------------------------------
__device__ __forceinline__ void mma_bf16(float* d, const uint32_t* a, uint32_t b0, uint32_t b1){
    asm("mma.sync.aligned.m16n8k16.row.col.f32.bf16.bf16.f32 "
        "{%0,%1,%2,%3},{%4,%5,%6,%7},{%8,%9},{%0,%1,%2,%3};"
        : "+f"(d[0]), "+f"(d[1]), "+f"(d[2]), "+f"(d[3])
        : "r"(a[0]), "r"(a[1]), "r"(a[2]), "r"(a[3]), "r"(b0), "r"(b1));
}
__device__ __forceinline__ void cp16(uint32_t s, const void* g){
    asm volatile("cp.async.cg.shared.global [%0], [%1], 16;" :: "r"(s), "l"(g));
}
__device__ __forceinline__ void split2(float v0, float v1, uint32_t& h, uint32_t& l){
    __nv_bfloat16 h0 = __float2bfloat16(v0), h1 = __float2bfloat16(v1);
    __nv_bfloat162 hp = __halves2bfloat162(h0, h1);
    __nv_bfloat162 lp = __halves2bfloat162(__float2bfloat16(v0 - __bfloat162float(h0)),
                                           __float2bfloat16(v1 - __bfloat162float(h1)));
    h = *(uint32_t*)&hp; l = *(uint32_t*)&lp;
}

// ---------------- prep: fp32 weights -> split-bf16 B-fragment order -----------
__global__ void prep_kernel(const float* __restrict__ W0, const float* __restrict__ Wh,
                            const float* __restrict__ Wl){
    int i = blockIdx.x * blockDim.x + threadIdx.x;
    const int NH = 7 * 28672, NL0 = 96 * 128, NF = 224 * 8;
    if (i >= NH + NL0 + NF) return;
    float v; uint32_t addr; int k, n;
    if (i < NH){
        int l = i / 28672, r = i % 28672; k = r / 128; n = r % 128;
        v = Wh[(l * 224 + k) * 128 + n];
        addr = (uint32_t)l * L_STRIDE + (uint32_t)(n >> 5) * C_STRIDE
             + (uint32_t)(((k >> 4) * 4 + ((n >> 3) & 3)) * 2) * 256u;
    } else if (i < NH + NL0){
        int q = i - NH; k = q / 128; n = q % 128;
        v = W0[k * 128 + n];
        addr = G_L0 + (uint32_t)(n >> 5) * L0_CSTRIDE
             + (uint32_t)(((k >> 4) * 4 + ((n >> 3) & 3)) * 2) * 256u;
    } else {
        int q = i - NH - NL0; k = q / 8; n = q % 8;
        v = (n < 4) ? Wl[k * 4 + n] : 0.0f;
        addr = G_FIN + (uint32_t)((k >> 4) * 2) * 256u;
    }
    uint32_t sub = (uint32_t)((n & 7) * 4 + ((k & 7) >> 1)) * 8u
                 + (uint32_t)((k >> 3) & 1) * 4u + (uint32_t)(k & 1) * 2u;
    __nv_bfloat16 hi = __float2bfloat16(v);
    __nv_bfloat16 lo = __float2bfloat16(v - __bfloat162float(hi));
    *(__nv_bfloat16*)(g_wt + addr + sub)        = hi;
    *(__nv_bfloat16*)(g_wt + addr + 256u + sub) = lo;
}

// ---------------- main fused kernel --------------------------------------------
__global__ void __launch_bounds__(THREADS, 1)
nf_main(const float* __restrict__ qp, const float* __restrict__ b0g,
        const float* __restrict__ bhg, const float* __restrict__ blg,
        float* __restrict__ out)
{
    extern __shared__ char smc[];
    const int tid = threadIdx.x, w = tid >> 5, lane = tid & 31;
    const int l4 = lane >> 2, lm = lane & 3;
    const int gp0 = blockIdx.x * NPTS;
    const uint32_t sb = (uint32_t)__cvta_generic_to_shared(smc);

    float* bias = (float*)(smc + OFF_BIAS);
    for (int i = tid; i < 1028; i += THREADS)
        bias[i] = (i < 128) ? b0g[i] : (i < 1024 ? bhg[i - 128] : blg[i - 1024]);

    // ---- NeRF encoding directly into A-fragment order (hi/lo planes) ----
    {
        float xa[2][3];
        #pragma unroll
        for (int r = 0; r < 2; r++)
            #pragma unroll
            for (int c = 0; c < 3; c++)
                xa[r][c] = __ldg(qp + (gp0 + w * 16 + l4 + r * 8) * 3 + c);
        #pragma unroll
        for (int j = 0; j < 6; j++){
            uint32_t H[4], L[4];
            #pragma unroll
            for (int g = 0; g < 2; g++){
                int kb = 16 * j + 2 * lm + g * 8;
                #pragma unroll
                for (int r = 0; r < 2; r++){
                    float v[2];
                    #pragma unroll
                    for (int e = 0; e < 2; e++){
                        int k = kb + e, c = k >> 5, t = k & 31;
                        float s, co;
                        sincosf(xa[r][c] * ((float)(1 << (t & 15)) * PI_F), &s, &co);
                        v[e] = (t < 16) ? s : co;
                    }
                    split2(v[0], v[1], H[g * 2 + r], L[g * 2 + r]);
                }
            }
            char* eb = smc + OFF_ENC + (uint32_t)((w * 6 + j) * 2) * 512u + lane * 16;
            *(uint4*)eb         = *(uint4*)H;
            *(uint4*)(eb + 512) = *(uint4*)L;
        }
    }
    __syncthreads();

    float acc[16][4];
    uint32_t Ah[8][4], Al[8][4];

    auto zero_acc = [&](){
        #pragma unroll
        for (int i = 0; i < 16; i++){ acc[i][0] = 0; acc[i][1] = 0; acc[i][2] = 0; acc[i][3] = 0; }
    };
    auto load_chunk = [&](const unsigned char* src, uint32_t bytes, int buf){
        uint32_t dst = sb + OFF_RING + (uint32_t)buf * C_STRIDE;
        for (uint32_t i = (uint32_t)tid * 16u; i < bytes; i += THREADS * 16u)
            cp16(dst + i, src + i);
        asm volatile("cp.async.commit_group;");
    };
    auto ldenc = [&](int j, uint32_t* H, uint32_t* L){
        const char* eb = smc + OFF_ENC + (uint32_t)((w * 6 + j) * 2) * 512u + lane * 16;
        *(uint4*)H = *(const uint4*)eb;
        *(uint4*)L = *(const uint4*)(eb + 512);
    };
    // one (j, chunk) step: 4 n-blocks x 3 passes = 12 MMAs, 8 LDS.64
    auto nb_block = [&](const char* fb, const uint32_t* AH, const uint32_t* AL, int cb){
        uint64_t b0 = *(const uint64_t*)(fb);
        uint64_t b1 = *(const uint64_t*)(fb + 512);
        uint64_t b2 = *(const uint64_t*)(fb + 1024);
        uint64_t b3 = *(const uint64_t*)(fb + 1536);
        mma_bf16(acc[cb+0], AH, (uint32_t)b0, (uint32_t)(b0 >> 32));
        mma_bf16(acc[cb+1], AH, (uint32_t)b1, (uint32_t)(b1 >> 32));
        mma_bf16(acc[cb+2], AH, (uint32_t)b2, (uint32_t)(b2 >> 32));
        mma_bf16(acc[cb+3], AH, (uint32_t)b3, (uint32_t)(b3 >> 32));
        mma_bf16(acc[cb+0], AL, (uint32_t)b0, (uint32_t)(b0 >> 32));
        mma_bf16(acc[cb+1], AL, (uint32_t)b1, (uint32_t)(b1 >> 32));
        mma_bf16(acc[cb+2], AL, (uint32_t)b2, (uint32_t)(b2 >> 32));
        mma_bf16(acc[cb+3], AL, (uint32_t)b3, (uint32_t)(b3 >> 32));
        uint64_t c0 = *(const uint64_t*)(fb + 256);
        uint64_t c1 = *(const uint64_t*)(fb + 768);
        uint64_t c2 = *(const uint64_t*)(fb + 1280);
        uint64_t c3 = *(const uint64_t*)(fb + 1792);
        mma_bf16(acc[cb+0], AH, (uint32_t)c0, (uint32_t)(c0 >> 32));
        mma_bf16(acc[cb+1], AH, (uint32_t)c1, (uint32_t)(c1 >> 32));
        mma_bf16(acc[cb+2], AH, (uint32_t)c2, (uint32_t)(c2 >> 32));
        mma_bf16(acc[cb+3], AH, (uint32_t)c3, (uint32_t)(c3 >> 32));
    };
    auto epilogue = [&](const float* bp){
        #pragma unroll
        for (int j = 0; j < 8; j++){
            float ba0 = bp[16*j + 2*lm],     ba1 = bp[16*j + 2*lm + 1];
            float bb0 = bp[16*j + 8 + 2*lm], bb1 = bp[16*j + 8 + 2*lm + 1];
            float v0 = fmaxf(acc[2*j][0] + ba0, 0.f);
            float v1 = fmaxf(acc[2*j][1] + ba1, 0.f);
            float v2 = fmaxf(acc[2*j][2] + ba0, 0.f);
            float v3 = fmaxf(acc[2*j][3] + ba1, 0.f);
            float u0 = fmaxf(acc[2*j+1][0] + bb0, 0.f);
            float u1 = fmaxf(acc[2*j+1][1] + bb1, 0.f);
            float u2 = fmaxf(acc[2*j+1][2] + bb0, 0.f);
            float u3 = fmaxf(acc[2*j+1][3] + bb1, 0.f);
            split2(v0, v1, Ah[j][0], Al[j][0]);
            split2(v2, v3, Ah[j][1], Al[j][1]);
            split2(u0, u1, Ah[j][2], Al[j][2]);
            split2(u2, u3, Ah[j][3], Al[j][3]);
        }
    };

    // ---- layer 0: enc(96) -> 128 ----
    zero_acc();
    load_chunk(g_wt + G_L0, L0_CSTRIDE, 0);
    #pragma unroll
    for (int c = 0; c < 4; c++){
        if (c < 3){ load_chunk(g_wt + G_L0 + (uint32_t)(c + 1) * L0_CSTRIDE, L0_CSTRIDE, (c + 1) & 1);
                    asm volatile("cp.async.wait_group 1;"); }
        else        asm volatile("cp.async.wait_group 0;");
        __syncthreads();
        {
            const char* rb = smc + OFF_RING + (uint32_t)(c & 1) * C_STRIDE;
            #pragma unroll
            for (int j = 0; j < 6; j++){
                uint32_t EH[4], EL[4]; ldenc(j, EH, EL);
                nb_block(rb + (uint32_t)(j * 4) * 512u + lane * 8, EH, EL, 4 * c);
            }
        }
        __syncthreads();
    }
    epilogue(bias);

    // ---- 7 hidden layers: [H(128)|enc(96)] -> 128 ----
    for (int l = 0; l < 7; l++){
        zero_acc();
        const unsigned char* ws = g_wt + (uint32_t)l * L_STRIDE;
        load_chunk(ws, C_STRIDE, 0);
        #pragma unroll
        for (int c = 0; c < 4; c++){
            if (c < 3){ load_chunk(ws + (uint32_t)(c + 1) * C_STRIDE, C_STRIDE, (c + 1) & 1);
                        asm volatile("cp.async.wait_group 1;"); }
            else        asm volatile("cp.async.wait_group 0;");
            __syncthreads();
            {
                const char* rb = smc + OFF_RING + (uint32_t)(c & 1) * C_STRIDE;
                #pragma unroll
                for (int j = 0; j < 14; j++){
                    const uint32_t *pAH, *pAL; uint32_t EH[4], EL[4];
                    if (j < 8){ pAH = Ah[j]; pAL = Al[j]; }
                    else      { ldenc(j - 8, EH, EL); pAH = EH; pAL = EL; }
                    nb_block(rb + (uint32_t)(j * 4) * 512u + lane * 8, pAH, pAL, 4 * c);
                }
            }
            __syncthreads();
        }
        epilogue(bias + 128 + l * 128);
    }

    // ---- final layer: [H|enc](224) -> 4 (N padded to 8) ----
    load_chunk(g_wt + G_FIN, 7168u, 0);
    asm volatile("cp.async.wait_group 0;");
    __syncthreads();
    float fac[4] = {0.f, 0.f, 0.f, 0.f};
    {
        const char* rb = smc + OFF_RING;
        #pragma unroll
        for (int j = 0; j < 14; j++){
            const uint32_t *pAH, *pAL; uint32_t EH[4], EL[4];
            if (j < 8){ pAH = Ah[j]; pAL = Al[j]; }
            else      { ldenc(j - 8, EH, EL); pAH = EH; pAL = EL; }
            const char* fb = rb + (uint32_t)(j * 2) * 256u + lane * 8;
            uint64_t bh = *(const uint64_t*)fb;
            uint64_t bl2 = *(const uint64_t*)(fb + 256);
            mma_bf16(fac, pAH, (uint32_t)bh,  (uint32_t)(bh  >> 32));
            mma_bf16(fac, pAL, (uint32_t)bh,  (uint32_t)(bh  >> 32));
            mma_bf16(fac, pAH, (uint32_t)bl2, (uint32_t)(bl2 >> 32));
        }
    }
    if (lm < 2){
        int n0 = 2 * lm;
        float bv0 = bias[1024 + n0], bv1 = bias[1024 + n0 + 1];
        int p0 = gp0 + w * 16 + l4;
        *(float2*)(out + p0 * 4 + n0)       = make_float2(fac[0] + bv0, fac[1] + bv1);
        *(float2*)(out + (p0 + 8) * 4 + n0) = make_float2(fac[2] + bv0, fac[3] + bv1);
    }
}

extern "C" void kernel_launch(void* const* d_in, const int* in_sizes, int n_in,
                              void* d_out, int out_size) {
    const float* qp = (const float*)d_in[0];
    const float* W0 = (const float*)d_in[1];
    const float* b0 = (const float*)d_in[2];
    const float* Wh = (const float*)d_in[3];
    const float* bh = (const float*)d_in[4];
    const float* Wl = (const float*)d_in[5];
    const float* bl = (const float*)d_in[6];
    float* out = (float*)d_out;

    int n = in_sizes[0] / 3;   // 524288
    const int NPREP = 7 * 28672 + 96 * 128 + 224 * 8;
    prep_kernel<<<(NPREP + 255) / 256, 256>>>(W0, Wh, Wl);
    cudaFuncSetAttribute(nf_main, cudaFuncAttributeMaxDynamicSharedMemorySize, (int)SMEM_TOT);
    nf_main<<<n / NPTS, THREADS, SMEM_TOT>>>(qp, b0, bh, bl, out);
}